// round 11
// baseline (speedup 1.0000x reference)
#include <cuda_runtime.h>
#include <cuda_fp16.h>
#include <math.h>
#include <stdint.h>

#define IN_DIM   2048
#define OUT_DIM  2048
#define RNK      4
#define LUTN     16
#define NORM_EPS 1e-6f
#define MAG_EPS  1e-6f

// GEMM config: single-pass fp16, K = 2048, mbarrier ring
#define NSTEP   64               // 2048 / 32
#define STAGES  5
#define DEPTH   3                // fill-ahead; slack = STAGES-DEPTH = 2 iters of warp slide
#define ROWB    80               // 32 fp16 = 64B data + 16B pad (5 coprime 8 -> conflict-free ldsm)
#define ATILE_BYTES (128 * ROWB) // 10240
#define STAGE_BYTES (2 * ATILE_BYTES)
#define SMEM_TOTAL  (128 + STAGES * STAGE_BYTES)   // 102528 -> 2 CTAs/SM

// ---------------- device scratch ----------------
__device__ float d_nA[RNK];
__device__ float d_nB[RNK];
__device__ float d_g[RNK];
__device__ __align__(1024) __half d_Ah[(size_t)8192 * IN_DIM];     // x as fp16 [M, 2048]
__device__ __align__(1024) __half d_Bh[(size_t)OUT_DIM * IN_DIM];  // W as fp16 [N, 2048]

// ---------------- PTX helpers (plain sm_103-safe: sm_80/sm_90 features) ----------------
__device__ __forceinline__ uint32_t smem_u32(const void* p) {
    uint32_t a;
    asm("{ .reg .u64 t; cvta.to.shared.u64 t, %1; cvt.u32.u64 %0, t; }" : "=r"(a) : "l"(p));
    return a;
}
#define CP_ASYNC16(s, g) \
    asm volatile("cp.async.cg.shared.global [%0], [%1], 16;" :: "r"(s), "l"(g) : "memory")
#define MBAR_INIT(a, c) \
    asm volatile("mbarrier.init.shared.b64 [%0], %1;" :: "r"(a), "r"(c) : "memory")
#define MBAR_ARRIVE(a) \
    asm volatile("mbarrier.arrive.shared.b64 _, [%0];" :: "r"(a) : "memory")
#define CP_MBAR_ARRIVE(a) \
    asm volatile("cp.async.mbarrier.arrive.noinc.shared.b64 [%0];" :: "r"(a) : "memory")

__device__ __forceinline__ void mbar_wait(uint32_t mbar, uint32_t parity) {
    asm volatile(
        "{\n\t.reg .pred P;\n\t"
        "W%=:\n\t"
        "mbarrier.try_wait.parity.acquire.cta.shared::cta.b64 P, [%0], %1, 0x989680;\n\t"
        "@P bra.uni D%=;\n\t"
        "bra.uni W%=;\n\t"
        "D%=:\n\t}"
        :: "r"(mbar), "r"(parity) : "memory");
}

__device__ __forceinline__ void ldm_x4(uint32_t& r0, uint32_t& r1, uint32_t& r2, uint32_t& r3,
                                       uint32_t addr) {
    asm volatile("ldmatrix.sync.aligned.m8n8.x4.shared.b16 {%0,%1,%2,%3}, [%4];"
                 : "=r"(r0), "=r"(r1), "=r"(r2), "=r"(r3) : "r"(addr));
}
__device__ __forceinline__ void mma_f16(float& c0, float& c1, float& c2, float& c3,
                                        uint32_t a0, uint32_t a1, uint32_t a2, uint32_t a3,
                                        uint32_t b0, uint32_t b1) {
    asm volatile(
        "mma.sync.aligned.m16n8k16.row.col.f32.f16.f16.f32 "
        "{%0,%1,%2,%3}, {%4,%5,%6,%7}, {%8,%9}, {%0,%1,%2,%3};"
        : "+f"(c0), "+f"(c1), "+f"(c2), "+f"(c3)
        : "r"(a0), "r"(a1), "r"(a2), "r"(a3), "r"(b0), "r"(b1));
}

// ---------------- kernel 1: rank norms + softplus magnitudes (2 fat blocks) ----------------
__global__ void prep_norms_kernel(const float* __restrict__ sA,
                                  const float* __restrict__ sB,
                                  const float* __restrict__ mag) {
    __shared__ float red[8][RNK];
    int tid = threadIdx.x, lane = tid & 31, w = tid >> 5;
    float s[RNK] = {0.f, 0.f, 0.f, 0.f};

    if (blockIdx.x == 0) {
        // sA [OUT, 4]: one float4 per row covers all 4 ranks, fully coalesced
        for (int o = tid; o < OUT_DIM; o += 256) {
            float4 v = *(const float4*)(sA + o * RNK);
            s[0] += v.x * v.x; s[1] += v.y * v.y; s[2] += v.z * v.z; s[3] += v.w * v.w;
        }
    } else {
        // sB [4, IN]: 4 coalesced row loads per thread
        for (int i = tid; i < IN_DIM; i += 256) {
            #pragma unroll
            for (int r = 0; r < RNK; r++) {
                float v = sB[r * IN_DIM + i];
                s[r] += v * v;
            }
        }
    }
    #pragma unroll
    for (int r = 0; r < RNK; r++) {
        #pragma unroll
        for (int off = 16; off; off >>= 1) s[r] += __shfl_xor_sync(0xffffffffu, s[r], off);
    }
    if (lane == 0) {
        #pragma unroll
        for (int r = 0; r < RNK; r++) red[w][r] = s[r];
    }
    __syncthreads();
    if (tid < RNK) {
        float t = 0.f;
        #pragma unroll
        for (int i = 0; i < 8; i++) t += red[i][tid];
        float n = fmaxf(sqrtf(t), NORM_EPS);
        if (blockIdx.x == 0) {
            d_nA[tid] = n;
            float m = mag[tid];
            float sp = (m > 20.f) ? m : log1pf(expf(m));
            d_g[tid] = sp + MAG_EPS;
        } else {
            d_nB[tid] = n;
        }
    }
}

// ---------------- kernel 2: fused convert (x -> fp16, 8/thread) + build W ----------------
__global__ void convert_kernel(const float* __restrict__ x,
                               const int* __restrict__ idx,
                               const float* __restrict__ lut,
                               const float* __restrict__ sA,
                               const float* __restrict__ sB,
                               int xblk) {
    if (blockIdx.x < (unsigned)xblk) {
        size_t t = (size_t)blockIdx.x * blockDim.x + threadIdx.x;
        size_t base = t * 8;
        float4 v0 = *(const float4*)(x + base);
        float4 v1 = *(const float4*)(x + base + 4);
        __half2 h0 = __floats2half2_rn(v0.x, v0.y);
        __half2 h1 = __floats2half2_rn(v0.z, v0.w);
        __half2 h2 = __floats2half2_rn(v1.x, v1.y);
        __half2 h3 = __floats2half2_rn(v1.z, v1.w);
        uint4 out;
        out.x = *(uint32_t*)&h0; out.y = *(uint32_t*)&h1;
        out.z = *(uint32_t*)&h2; out.w = *(uint32_t*)&h3;
        *(uint4*)&d_Ah[base] = out;
        return;
    }
    __shared__ float lutS[LUTN];
    if (threadIdx.x < LUTN) lutS[threadIdx.x] = lut[threadIdx.x];
    __syncthreads();

    size_t t = (size_t)(blockIdx.x - xblk) * blockDim.x + threadIdx.x;
    size_t base = t * 8;
    int o = (int)(base >> 11);
    int i0 = (int)(base & 2047);

    float cA[RNK];
    #pragma unroll
    for (int r = 0; r < RNK; r++)
        cA[r] = fabsf(sA[o * RNK + r]) * d_g[r] / (d_nA[r] * d_nB[r]);

    int4 idA = *(const int4*)(idx + (size_t)o * IN_DIM + i0);
    int4 idB = *(const int4*)(idx + (size_t)o * IN_DIM + i0 + 4);
    int ids[8] = {idA.x, idA.y, idA.z, idA.w, idB.x, idB.y, idB.z, idB.w};
    float w[8];
    #pragma unroll
    for (int j = 0; j < 8; j++) {
        int i = i0 + j;
        float s = 0.f;
        #pragma unroll
        for (int r = 0; r < RNK; r++)
            s += cA[r] * fabsf(sB[r * IN_DIM + i]);
        w[j] = lutS[ids[j]] * s;
    }
    __half2 h0 = __floats2half2_rn(w[0], w[1]);
    __half2 h1 = __floats2half2_rn(w[2], w[3]);
    __half2 h2 = __floats2half2_rn(w[4], w[5]);
    __half2 h3 = __floats2half2_rn(w[6], w[7]);
    uint4 out;
    out.x = *(uint32_t*)&h0; out.y = *(uint32_t*)&h1;
    out.z = *(uint32_t*)&h2; out.w = *(uint32_t*)&h3;
    *(uint4*)&d_Bh[base] = out;
}

// ---------------- kernel 3: fp16 GEMM, mbarrier ring, CTA 128x128, 2 CTAs/SM ----------------
__global__ __launch_bounds__(256, 2)
void gemm_kernel(const float* __restrict__ bias, float* __restrict__ y) {
    extern __shared__ char smem[];
    const uint32_t sbase = smem_u32(smem);
    const uint32_t mbF = sbase;           // full[5]
    const uint32_t mbE = sbase + 64;      // empty[5]
    const uint32_t dbase = sbase + 128;

    const int tid = threadIdx.x, lane = tid & 31, wid = tid >> 5;
    const int warp_m = wid & 1, warp_n = wid >> 1;     // 2 x 4 warps, 64x32 warp tiles
    const int m0 = blockIdx.y * 128, n0 = blockIdx.x * 128;

    const int lr = tid >> 2, lc = tid & 3;
    const __half* Ag = d_Ah + (size_t)m0 * IN_DIM;
    const __half* Bg = d_Bh + (size_t)n0 * IN_DIM;

    const uint32_t aLaneOff = (uint32_t)(lane & 15) * ROWB + (uint32_t)(lane >> 4) * 16;
    const uint32_t bLaneOff = (uint32_t)((lane & 7) + ((lane >> 4) << 3)) * ROWB
                            + (uint32_t)((lane >> 3) & 1) * 16;

    if (tid == 0) {
        #pragma unroll
        for (int s = 0; s < STAGES; s++) {
            MBAR_INIT(mbF + s * 8, 256);   // every thread's cp.async arrive (noinc)
            MBAR_INIT(mbE + s * 8, 8);     // one arrive per warp
        }
    }
    __syncthreads();

    float acc[4][4][4];
    #pragma unroll
    for (int i = 0; i < 4; i++)
        #pragma unroll
        for (int j = 0; j < 4; j++)
            #pragma unroll
            for (int q = 0; q < 4; q++) acc[i][j][q] = 0.f;

    auto issue_cp = [&](int t, int slot) {
        int kk = t << 5;
        uint32_t sA = dbase + slot * STAGE_BYTES;
        uint32_t sB = sA + ATILE_BYTES;
        CP_ASYNC16(sA + lr * ROWB + lc * 16,
                   (const char*)(Ag + (size_t)lr * IN_DIM + kk + lc * 8));
        CP_ASYNC16(sA + (lr + 64) * ROWB + lc * 16,
                   (const char*)(Ag + (size_t)(lr + 64) * IN_DIM + kk + lc * 8));
        CP_ASYNC16(sB + lr * ROWB + lc * 16,
                   (const char*)(Bg + (size_t)lr * IN_DIM + kk + lc * 8));
        CP_ASYNC16(sB + (lr + 64) * ROWB + lc * 16,
                   (const char*)(Bg + (size_t)(lr + 64) * IN_DIM + kk + lc * 8));
        CP_MBAR_ARRIVE(mbF + slot * 8);
    };

    // prologue: fill chunks 0..DEPTH-1 into slots 0..DEPTH-1
    #pragma unroll
    for (int f = 0; f < DEPTH; f++) issue_cp(f, f);

    int cs = 0, cpar = 0;      // consumer slot/parity
    int ps = DEPTH, ppar = 0;  // producer slot/parity

    for (int t = 0; t < NSTEP; t++) {
        int tf = t + DEPTH;
        if (tf < NSTEP) {
            if (tf >= STAGES) mbar_wait(mbE + ps * 8, ppar ^ 1);  // slot free?
            issue_cp(tf, ps);
            if (++ps == STAGES) { ps = 0; ppar ^= 1; }
        }

        mbar_wait(mbF + cs * 8, cpar);   // chunk t data ready (acquire)

        uint32_t sA = dbase + cs * STAGE_BYTES + (uint32_t)(warp_m * 64) * ROWB + aLaneOff;
        uint32_t sB = dbase + cs * STAGE_BYTES + ATILE_BYTES
                    + (uint32_t)(warp_n * 32) * ROWB + bLaneOff;
        #pragma unroll
        for (int k16 = 0; k16 < 2; k16++) {
            uint32_t a[4][4], b[2][4];
            #pragma unroll
            for (int mi = 0; mi < 4; mi++)
                ldm_x4(a[mi][0], a[mi][1], a[mi][2], a[mi][3],
                       sA + (uint32_t)(mi * 16) * ROWB + k16 * 32);
            #pragma unroll
            for (int p = 0; p < 2; p++)
                ldm_x4(b[p][0], b[p][1], b[p][2], b[p][3],
                       sB + (uint32_t)(p * 16) * ROWB + k16 * 32);
            #pragma unroll
            for (int mi = 0; mi < 4; mi++)
                #pragma unroll
                for (int ni = 0; ni < 4; ni++) {
                    uint32_t b0 = b[ni >> 1][(ni & 1) * 2];
                    uint32_t b1 = b[ni >> 1][(ni & 1) * 2 + 1];
                    mma_f16(acc[mi][ni][0], acc[mi][ni][1], acc[mi][ni][2], acc[mi][ni][3],
                            a[mi][0], a[mi][1], a[mi][2], a[mi][3], b0, b1);
                }
        }

        __syncwarp();
        if (lane == 0) MBAR_ARRIVE(mbE + cs * 8);   // this warp done with slot cs
        if (++cs == STAGES) { cs = 0; cpar ^= 1; }
    }

    // ---- epilogue: + bias, float2 stores (per-warp independent) ----
    #pragma unroll
    for (int ni = 0; ni < 4; ni++) {
        int col = n0 + warp_n * 32 + ni * 8 + (lane & 3) * 2;
        float2 bb = *(const float2*)(bias + col);
        #pragma unroll
        for (int mi = 0; mi < 4; mi++) {
            int r0 = m0 + warp_m * 64 + mi * 16 + (lane >> 2);
            float2 v0, v1;
            v0.x = acc[mi][ni][0] + bb.x; v0.y = acc[mi][ni][1] + bb.y;
            v1.x = acc[mi][ni][2] + bb.x; v1.y = acc[mi][ni][3] + bb.y;
            *(float2*)(y + (size_t)r0 * OUT_DIM + col)       = v0;
            *(float2*)(y + (size_t)(r0 + 8) * OUT_DIM + col) = v1;
        }
    }
}

// ---------------- host ----------------
extern "C" void kernel_launch(void* const* d_in, const int* in_sizes, int n_in,
                              void* d_out, int out_size) {
    const float* x       = (const float*)d_in[0];
    const int*   indices = (const int*)d_in[1];
    const float* lut     = (const float*)d_in[2];
    const float* sA      = (const float*)d_in[3];
    const float* sB      = (const float*)d_in[4];
    const float* mag     = (const float*)d_in[5];
    const float* bias    = (const float*)d_in[6];
    float*       y       = (float*)d_out;

    int M = in_sizes[0] / IN_DIM;   // 8192
    int xblk = (int)((size_t)M * IN_DIM / 8 / 256);          // 8192
    int wblk = (OUT_DIM * IN_DIM / 8) / 256;                 // 1024

    cudaFuncSetAttribute(gemm_kernel, cudaFuncAttributeMaxDynamicSharedMemorySize, SMEM_TOTAL);

    prep_norms_kernel<<<2, 256>>>(sA, sB, mag);
    convert_kernel<<<xblk + wblk, 256>>>(x, indices, lut, sA, sB, xblk);
    gemm_kernel<<<dim3(OUT_DIM / 128, M / 128), 256, SMEM_TOTAL>>>(bias, y);
}

// round 12
// speedup vs baseline: 1.0050x; 1.0050x over previous
#include <cuda_runtime.h>
#include <cuda_fp16.h>
#include <math.h>
#include <stdint.h>

#define IN_DIM   2048
#define OUT_DIM  2048
#define RNK      4
#define LUTN     16
#define NORM_EPS 1e-6f
#define MAG_EPS  1e-6f

// GEMM config: single-pass fp16, K = 2048, mbarrier ring, split-K tail
#define STAGES  5
#define DEPTH   3                // fill-ahead; slack = STAGES-DEPTH = 2 iters of warp slide
#define ROWB    80               // 32 fp16 = 64B data + 16B pad (5 coprime 8 -> conflict-free ldsm)
#define ATILE_BYTES (128 * ROWB) // 10240
#define STAGE_BYTES (2 * ATILE_BYTES)
#define SMEM_TOTAL  (128 + STAGES * STAGE_BYTES)   // 102528 -> 2 CTAs/SM
#define SPLIT_MROWS 8            // last 8 tile-rows get split-K x2

// ---------------- device scratch ----------------
__device__ float d_nA[RNK];
__device__ float d_nB[RNK];
__device__ float d_g[RNK];
__device__ __align__(1024) __half d_Ah[(size_t)8192 * IN_DIM];     // x as fp16 [M, 2048]
__device__ __align__(1024) __half d_Bh[(size_t)OUT_DIM * IN_DIM];  // W as fp16 [N, 2048]

// ---------------- PTX helpers (plain sm_103-safe: sm_80/sm_90 features) ----------------
__device__ __forceinline__ uint32_t smem_u32(const void* p) {
    uint32_t a;
    asm("{ .reg .u64 t; cvta.to.shared.u64 t, %1; cvt.u32.u64 %0, t; }" : "=r"(a) : "l"(p));
    return a;
}
#define CP_ASYNC16(s, g) \
    asm volatile("cp.async.cg.shared.global [%0], [%1], 16;" :: "r"(s), "l"(g) : "memory")
#define MBAR_INIT(a, c) \
    asm volatile("mbarrier.init.shared.b64 [%0], %1;" :: "r"(a), "r"(c) : "memory")
#define MBAR_ARRIVE(a) \
    asm volatile("mbarrier.arrive.shared.b64 _, [%0];" :: "r"(a) : "memory")
#define CP_MBAR_ARRIVE(a) \
    asm volatile("cp.async.mbarrier.arrive.noinc.shared.b64 [%0];" :: "r"(a) : "memory")

__device__ __forceinline__ void mbar_wait(uint32_t mbar, uint32_t parity) {
    asm volatile(
        "{\n\t.reg .pred P;\n\t"
        "W%=:\n\t"
        "mbarrier.try_wait.parity.acquire.cta.shared::cta.b64 P, [%0], %1, 0x989680;\n\t"
        "@P bra.uni D%=;\n\t"
        "bra.uni W%=;\n\t"
        "D%=:\n\t}"
        :: "r"(mbar), "r"(parity) : "memory");
}

__device__ __forceinline__ void ldm_x4(uint32_t& r0, uint32_t& r1, uint32_t& r2, uint32_t& r3,
                                       uint32_t addr) {
    asm volatile("ldmatrix.sync.aligned.m8n8.x4.shared.b16 {%0,%1,%2,%3}, [%4];"
                 : "=r"(r0), "=r"(r1), "=r"(r2), "=r"(r3) : "r"(addr));
}
__device__ __forceinline__ void mma_f16(float& c0, float& c1, float& c2, float& c3,
                                        uint32_t a0, uint32_t a1, uint32_t a2, uint32_t a3,
                                        uint32_t b0, uint32_t b1) {
    asm volatile(
        "mma.sync.aligned.m16n8k16.row.col.f32.f16.f16.f32 "
        "{%0,%1,%2,%3}, {%4,%5,%6,%7}, {%8,%9}, {%0,%1,%2,%3};"
        : "+f"(c0), "+f"(c1), "+f"(c2), "+f"(c3)
        : "r"(a0), "r"(a1), "r"(a2), "r"(a3), "r"(b0), "r"(b1));
}

// ---------------- kernel 1: rank norms + softplus + zero split-K region ----------------
__global__ void prep_norms_kernel(const float* __restrict__ sA,
                                  const float* __restrict__ sB,
                                  const float* __restrict__ mag,
                                  float* __restrict__ y, int zrow0) {
    int b = blockIdx.x;
    if (b >= 8) {
        // zero y rows [zrow0, M): 16B per thread
        size_t off = (size_t)zrow0 * OUT_DIM + (size_t)(b - 8) * (256 * 4) + threadIdx.x * 4;
        *(float4*)(y + off) = make_float4(0.f, 0.f, 0.f, 0.f);
        return;
    }
    __shared__ float red[8];
    int tid = threadIdx.x, lane = tid & 31, w = tid >> 5;
    int r = b & 3;
    float s = 0.f;
    if (b < 4) {
        for (int o = tid; o < OUT_DIM; o += 256) { float v = sA[o * RNK + r]; s += v * v; }
    } else {
        for (int i = tid; i < IN_DIM; i += 256) { float v = sB[r * IN_DIM + i]; s += v * v; }
    }
    #pragma unroll
    for (int off = 16; off; off >>= 1) s += __shfl_xor_sync(0xffffffffu, s, off);
    if (lane == 0) red[w] = s;
    __syncthreads();
    if (tid == 0) {
        float t = 0.f;
        #pragma unroll
        for (int i = 0; i < 8; i++) t += red[i];
        float n = fmaxf(sqrtf(t), NORM_EPS);
        if (b < 4) d_nA[r] = n; else d_nB[r] = n;
        if (b == 0) {
            #pragma unroll
            for (int q = 0; q < RNK; q++) {
                float m = mag[q];
                float sp = (m > 20.f) ? m : log1pf(expf(m));
                d_g[q] = sp + MAG_EPS;
            }
        }
    }
}

// ---------------- kernel 2: fused convert (x -> fp16) + build W (-> fp16) ----------------
__global__ void convert_kernel(const float* __restrict__ x,
                               const int* __restrict__ idx,
                               const float* __restrict__ lut,
                               const float* __restrict__ sA,
                               const float* __restrict__ sB,
                               int xblk) {
    if (blockIdx.x < (unsigned)xblk) {
        size_t t = (size_t)blockIdx.x * blockDim.x + threadIdx.x;
        size_t base = t * 4;
        float4 v = *(const float4*)(x + base);
        __half2 h0 = __floats2half2_rn(v.x, v.y);
        __half2 h1 = __floats2half2_rn(v.z, v.w);
        *(uint2*)&d_Ah[base] = make_uint2(*(uint32_t*)&h0, *(uint32_t*)&h1);
        return;
    }
    __shared__ float lutS[LUTN];
    if (threadIdx.x < LUTN) lutS[threadIdx.x] = lut[threadIdx.x];
    __syncthreads();

    size_t t = (size_t)(blockIdx.x - xblk) * blockDim.x + threadIdx.x;
    size_t base = t * 4;
    int o = (int)(base >> 11);
    int i0 = (int)(base & 2047);

    float cA[RNK];
    #pragma unroll
    for (int r = 0; r < RNK; r++)
        cA[r] = fabsf(sA[o * RNK + r]) * d_g[r] / (d_nA[r] * d_nB[r]);

    int4 id4 = *(const int4*)(idx + (size_t)o * IN_DIM + i0);
    int ids[4] = {id4.x, id4.y, id4.z, id4.w};
    float w[4];
    #pragma unroll
    for (int j = 0; j < 4; j++) {
        int i = i0 + j;
        float s = 0.f;
        #pragma unroll
        for (int r = 0; r < RNK; r++)
            s += cA[r] * fabsf(sB[r * IN_DIM + i]);
        w[j] = lutS[ids[j]] * s;
    }
    __half2 h0 = __floats2half2_rn(w[0], w[1]);
    __half2 h1 = __floats2half2_rn(w[2], w[3]);
    *(uint2*)&d_Bh[base] = make_uint2(*(uint32_t*)&h0, *(uint32_t*)&h1);
}

// ---------------- kernel 3: fp16 GEMM, mbarrier ring, split-K tail ----------------
__global__ __launch_bounds__(256, 2)
void gemm_kernel(const float* __restrict__ bias, float* __restrict__ y, int mx0) {
    extern __shared__ char smem[];
    const uint32_t sbase = smem_u32(smem);
    const uint32_t mbF = sbase;           // full[5]
    const uint32_t mbE = sbase + 64;      // empty[5]
    const uint32_t dbase = sbase + 128;

    const int tid = threadIdx.x, lane = tid & 31, wid = tid >> 5;
    const int warp_m = wid & 1, warp_n = wid >> 1;     // 2 x 4 warps, 64x32 warp tiles

    // ---- tile decode: full-K tiles first, then split-K tail tiles ----
    const int bid = blockIdx.x;
    const int fullCnt = mx0 * 16;
    int mx, nx, kbase, nstep, kh;
    bool isfull;
    if (bid < fullCnt) {
        mx = bid >> 4; nx = bid & 15;
        kbase = 0; nstep = 64; kh = 0; isfull = true;
    } else {
        int sub = bid - fullCnt;
        int tt = sub >> 1; kh = sub & 1;
        mx = mx0 + (tt >> 4); nx = tt & 15;
        kbase = kh << 10; nstep = 32; isfull = false;
    }
    const int m0 = mx * 128, n0 = nx * 128;

    const int lr = tid >> 2, lc = tid & 3;
    const __half* Ag = d_Ah + (size_t)m0 * IN_DIM + kbase;
    const __half* Bg = d_Bh + (size_t)n0 * IN_DIM + kbase;

    const uint32_t aLaneOff = (uint32_t)(lane & 15) * ROWB + (uint32_t)(lane >> 4) * 16;
    const uint32_t bLaneOff = (uint32_t)((lane & 7) + ((lane >> 4) << 3)) * ROWB
                            + (uint32_t)((lane >> 3) & 1) * 16;

    if (tid == 0) {
        #pragma unroll
        for (int s = 0; s < STAGES; s++) {
            MBAR_INIT(mbF + s * 8, 256);   // every thread's cp.async arrive (noinc)
            MBAR_INIT(mbE + s * 8, 8);     // one arrive per warp
        }
    }
    __syncthreads();

    float acc[4][4][4];
    #pragma unroll
    for (int i = 0; i < 4; i++)
        #pragma unroll
        for (int j = 0; j < 4; j++)
            #pragma unroll
            for (int q = 0; q < 4; q++) acc[i][j][q] = 0.f;

    auto issue_cp = [&](int t, int slot) {
        int kk = t << 5;
        uint32_t sA = dbase + slot * STAGE_BYTES;
        uint32_t sB = sA + ATILE_BYTES;
        CP_ASYNC16(sA + lr * ROWB + lc * 16,
                   (const char*)(Ag + (size_t)lr * IN_DIM + kk + lc * 8));
        CP_ASYNC16(sA + (lr + 64) * ROWB + lc * 16,
                   (const char*)(Ag + (size_t)(lr + 64) * IN_DIM + kk + lc * 8));
        CP_ASYNC16(sB + lr * ROWB + lc * 16,
                   (const char*)(Bg + (size_t)lr * IN_DIM + kk + lc * 8));
        CP_ASYNC16(sB + (lr + 64) * ROWB + lc * 16,
                   (const char*)(Bg + (size_t)(lr + 64) * IN_DIM + kk + lc * 8));
        CP_MBAR_ARRIVE(mbF + slot * 8);
    };

    // prologue: fill chunks 0..DEPTH-1 into slots 0..DEPTH-1
    #pragma unroll
    for (int f = 0; f < DEPTH; f++) issue_cp(f, f);

    int cs = 0, cpar = 0;      // consumer slot/parity
    int ps = DEPTH, ppar = 0;  // producer slot/parity

    for (int t = 0; t < nstep; t++) {
        int tf = t + DEPTH;
        if (tf < nstep) {
            if (tf >= STAGES) mbar_wait(mbE + ps * 8, ppar ^ 1);  // slot free?
            issue_cp(tf, ps);
            if (++ps == STAGES) { ps = 0; ppar ^= 1; }
        }

        mbar_wait(mbF + cs * 8, cpar);   // chunk t data ready (acquire)

        uint32_t sA = dbase + cs * STAGE_BYTES + (uint32_t)(warp_m * 64) * ROWB + aLaneOff;
        uint32_t sB = dbase + cs * STAGE_BYTES + ATILE_BYTES
                    + (uint32_t)(warp_n * 32) * ROWB + bLaneOff;
        #pragma unroll
        for (int k16 = 0; k16 < 2; k16++) {
            uint32_t a[4][4], b[2][4];
            #pragma unroll
            for (int mi = 0; mi < 4; mi++)
                ldm_x4(a[mi][0], a[mi][1], a[mi][2], a[mi][3],
                       sA + (uint32_t)(mi * 16) * ROWB + k16 * 32);
            #pragma unroll
            for (int p = 0; p < 2; p++)
                ldm_x4(b[p][0], b[p][1], b[p][2], b[p][3],
                       sB + (uint32_t)(p * 16) * ROWB + k16 * 32);
            #pragma unroll
            for (int mi = 0; mi < 4; mi++)
                #pragma unroll
                for (int ni = 0; ni < 4; ni++) {
                    uint32_t b0 = b[ni >> 1][(ni & 1) * 2];
                    uint32_t b1 = b[ni >> 1][(ni & 1) * 2 + 1];
                    mma_f16(acc[mi][ni][0], acc[mi][ni][1], acc[mi][ni][2], acc[mi][ni][3],
                            a[mi][0], a[mi][1], a[mi][2], a[mi][3], b0, b1);
                }
        }

        __syncwarp();
        if (lane == 0) MBAR_ARRIVE(mbE + cs * 8);   // this warp done with slot cs
        if (++cs == STAGES) { cs = 0; cpar ^= 1; }
    }

    // ---- epilogue ----
    #pragma unroll
    for (int ni = 0; ni < 4; ni++) {
        int col = n0 + warp_n * 32 + ni * 8 + (lane & 3) * 2;
        float2 bb;
        if (isfull || kh == 0) bb = *(const float2*)(bias + col);
        else                   bb = make_float2(0.f, 0.f);
        #pragma unroll
        for (int mi = 0; mi < 4; mi++) {
            int r0 = m0 + warp_m * 64 + mi * 16 + (lane >> 2);
            float2 v0, v1;
            v0.x = acc[mi][ni][0] + bb.x; v0.y = acc[mi][ni][1] + bb.y;
            v1.x = acc[mi][ni][2] + bb.x; v1.y = acc[mi][ni][3] + bb.y;
            float* p0 = y + (size_t)r0 * OUT_DIM + col;
            float* p1 = y + (size_t)(r0 + 8) * OUT_DIM + col;
            if (isfull) {
                *(float2*)p0 = v0;
                *(float2*)p1 = v1;
            } else {
                atomicAdd(p0,     v0.x); atomicAdd(p0 + 1, v0.y);
                atomicAdd(p1,     v1.x); atomicAdd(p1 + 1, v1.y);
            }
        }
    }
}

// ---------------- host ----------------
extern "C" void kernel_launch(void* const* d_in, const int* in_sizes, int n_in,
                              void* d_out, int out_size) {
    const float* x       = (const float*)d_in[0];
    const int*   indices = (const int*)d_in[1];
    const float* lut     = (const float*)d_in[2];
    const float* sA      = (const float*)d_in[3];
    const float* sB      = (const float*)d_in[4];
    const float* mag     = (const float*)d_in[5];
    const float* bias    = (const float*)d_in[6];
    float*       y       = (float*)d_out;

    int M = in_sizes[0] / IN_DIM;   // 8192
    int xblk = (int)((size_t)M * IN_DIM / 4 / 256);          // 16384
    int wblk = (OUT_DIM * IN_DIM / 4) / 256;                 // 4096

    int mtiles = M / 128;                         // 64
    int mx0 = mtiles - SPLIT_MROWS;               // 56: full-K tile rows
    int zrow0 = mx0 * 128;                        // 7168
    int zblk = (M - zrow0) * OUT_DIM / (256 * 4); // 2048 zero blocks (16B/thread)
    int grid = mx0 * 16 + SPLIT_MROWS * 16 * 2;   // 896 + 256 = 1152

    cudaFuncSetAttribute(gemm_kernel, cudaFuncAttributeMaxDynamicSharedMemorySize, SMEM_TOTAL);

    prep_norms_kernel<<<8 + zblk, 256>>>(sA, sB, mag, y, zrow0);
    convert_kernel<<<xblk + wblk, 256>>>(x, indices, lut, sA, sB, xblk);
    gemm_kernel<<<grid, 256, SMEM_TOTAL>>>(bias, y, mx0);
}

// round 13
// speedup vs baseline: 1.0155x; 1.0104x over previous
#include <cuda_runtime.h>
#include <cuda_fp16.h>
#include <math.h>
#include <stdint.h>

#define IN_DIM   2048
#define OUT_DIM  2048
#define RNK      4
#define LUTN     16
#define NORM_EPS 1e-6f
#define MAG_EPS  1e-6f

// GEMM config: single-pass fp16, K = 2048, mbarrier ring (R9-proven)
#define NSTEP   64               // 2048 / 32
#define STAGES  5
#define DEPTH   3                // fill-ahead; slack = STAGES-DEPTH = 2 iters of warp slide
#define ROWB    80               // 32 fp16 = 64B data + 16B pad (5 coprime 8 -> conflict-free ldsm)
#define ATILE_BYTES (128 * ROWB) // 10240
#define STAGE_BYTES (2 * ATILE_BYTES)
#define SMEM_TOTAL  (128 + STAGES * STAGE_BYTES)   // 102528 -> 2 CTAs/SM

// ---------------- device scratch ----------------
__device__ float d_nA[RNK];
__device__ float d_nB[RNK];
__device__ float d_g[RNK];
__device__ int   d_done = 0;     // prep->W ordering flag; reset by gemm_kernel each launch
__device__ __align__(1024) __half d_Ah[(size_t)8192 * IN_DIM];     // x as fp16 [M, 2048]
__device__ __align__(1024) __half d_Bh[(size_t)OUT_DIM * IN_DIM];  // W as fp16 [N, 2048]

// ---------------- PTX helpers (plain sm_103-safe: sm_80/sm_90 features) ----------------
__device__ __forceinline__ uint32_t smem_u32(const void* p) {
    uint32_t a;
    asm("{ .reg .u64 t; cvta.to.shared.u64 t, %1; cvt.u32.u64 %0, t; }" : "=r"(a) : "l"(p));
    return a;
}
#define CP_ASYNC16(s, g) \
    asm volatile("cp.async.cg.shared.global [%0], [%1], 16;" :: "r"(s), "l"(g) : "memory")
#define MBAR_INIT(a, c) \
    asm volatile("mbarrier.init.shared.b64 [%0], %1;" :: "r"(a), "r"(c) : "memory")
#define MBAR_ARRIVE(a) \
    asm volatile("mbarrier.arrive.shared.b64 _, [%0];" :: "r"(a) : "memory")
#define CP_MBAR_ARRIVE(a) \
    asm volatile("cp.async.mbarrier.arrive.noinc.shared.b64 [%0];" :: "r"(a) : "memory")

__device__ __forceinline__ void mbar_wait(uint32_t mbar, uint32_t parity) {
    asm volatile(
        "{\n\t.reg .pred P;\n\t"
        "W%=:\n\t"
        "mbarrier.try_wait.parity.acquire.cta.shared::cta.b64 P, [%0], %1, 0x989680;\n\t"
        "@P bra.uni D%=;\n\t"
        "bra.uni W%=;\n\t"
        "D%=:\n\t}"
        :: "r"(mbar), "r"(parity) : "memory");
}

__device__ __forceinline__ void ldm_x4(uint32_t& r0, uint32_t& r1, uint32_t& r2, uint32_t& r3,
                                       uint32_t addr) {
    asm volatile("ldmatrix.sync.aligned.m8n8.x4.shared.b16 {%0,%1,%2,%3}, [%4];"
                 : "=r"(r0), "=r"(r1), "=r"(r2), "=r"(r3) : "r"(addr));
}
__device__ __forceinline__ void mma_f16(float& c0, float& c1, float& c2, float& c3,
                                        uint32_t a0, uint32_t a1, uint32_t a2, uint32_t a3,
                                        uint32_t b0, uint32_t b1) {
    asm volatile(
        "mma.sync.aligned.m16n8k16.row.col.f32.f16.f16.f32 "
        "{%0,%1,%2,%3}, {%4,%5,%6,%7}, {%8,%9}, {%0,%1,%2,%3};"
        : "+f"(c0), "+f"(c1), "+f"(c2), "+f"(c3)
        : "r"(a0), "r"(a1), "r"(a2), "r"(a3), "r"(b0), "r"(b1));
}

// ---------------- kernel 1: fused prep-norms + convert x + build W ----------------
// bid [0,8): rank norms + softplus  -> arrive on d_done
// bid [8, 8+xblk): x -> fp16        (no dependency)
// bid [8+xblk, ...): build W        (spins on d_done == 8; scheduled last)
__global__ void convert_kernel(const float* __restrict__ x,
                               const int* __restrict__ idx,
                               const float* __restrict__ lut,
                               const float* __restrict__ sA,
                               const float* __restrict__ sB,
                               const float* __restrict__ mag,
                               int xblk) {
    const int bid = blockIdx.x;

    if (bid < 8) {
        // ---- norms ----
        __shared__ float red[8];
        int tid = threadIdx.x, lane = tid & 31, w = tid >> 5;
        int r = bid & 3;
        float s = 0.f;
        if (bid < 4) {
            for (int o = tid; o < OUT_DIM; o += 256) { float v = sA[o * RNK + r]; s += v * v; }
        } else {
            for (int i = tid; i < IN_DIM; i += 256) { float v = sB[r * IN_DIM + i]; s += v * v; }
        }
        #pragma unroll
        for (int off = 16; off; off >>= 1) s += __shfl_xor_sync(0xffffffffu, s, off);
        if (lane == 0) red[w] = s;
        __syncthreads();
        if (tid == 0) {
            float t = 0.f;
            #pragma unroll
            for (int i = 0; i < 8; i++) t += red[i];
            float n = fmaxf(sqrtf(t), NORM_EPS);
            if (bid < 4) d_nA[r] = n; else d_nB[r] = n;
            if (bid == 0) {
                #pragma unroll
                for (int q = 0; q < RNK; q++) {
                    float m = mag[q];
                    float sp = (m > 20.f) ? m : log1pf(expf(m));
                    d_g[q] = sp + MAG_EPS;
                }
            }
            __threadfence();
            atomicAdd(&d_done, 1);
        }
        return;
    }

    if (bid < 8 + xblk) {
        // ---- x -> fp16 ----
        size_t t = (size_t)(bid - 8) * blockDim.x + threadIdx.x;
        size_t base = t * 4;
        float4 v = *(const float4*)(x + base);
        __half2 h0 = __floats2half2_rn(v.x, v.y);
        __half2 h1 = __floats2half2_rn(v.z, v.w);
        *(uint2*)&d_Ah[base] = make_uint2(*(uint32_t*)&h0, *(uint32_t*)&h1);
        return;
    }

    // ---- build W (needs norms) ----
    __shared__ float lutS[LUTN];
    if (threadIdx.x < LUTN) lutS[threadIdx.x] = lut[threadIdx.x];
    if (threadIdx.x == 0) {
        while (atomicAdd(&d_done, 0) < 8) {}
        __threadfence();
    }
    __syncthreads();

    size_t t = (size_t)(bid - 8 - xblk) * blockDim.x + threadIdx.x;
    size_t base = t * 4;
    int o = (int)(base >> 11);
    int i0 = (int)(base & 2047);

    float cA[RNK];
    #pragma unroll
    for (int r = 0; r < RNK; r++)
        cA[r] = fabsf(sA[o * RNK + r]) * d_g[r] / (d_nA[r] * d_nB[r]);

    int4 id4 = *(const int4*)(idx + (size_t)o * IN_DIM + i0);
    int ids[4] = {id4.x, id4.y, id4.z, id4.w};
    float w[4];
    #pragma unroll
    for (int j = 0; j < 4; j++) {
        int i = i0 + j;
        float s = 0.f;
        #pragma unroll
        for (int r = 0; r < RNK; r++)
            s += cA[r] * fabsf(sB[r * IN_DIM + i]);
        w[j] = lutS[ids[j]] * s;
    }
    __half2 h0 = __floats2half2_rn(w[0], w[1]);
    __half2 h1 = __floats2half2_rn(w[2], w[3]);
    *(uint2*)&d_Bh[base] = make_uint2(*(uint32_t*)&h0, *(uint32_t*)&h1);
}

// ---------------- kernel 2: fp16 GEMM, mbarrier ring, CTA 128x128, 2 CTAs/SM ----------------
__global__ __launch_bounds__(256, 2)
void gemm_kernel(const float* __restrict__ bias, float* __restrict__ y) {
    // reset the prep flag for the NEXT launch (stream-ordered after convert consumed it)
    if (blockIdx.x == 0 && blockIdx.y == 0 && threadIdx.x == 0) d_done = 0;

    extern __shared__ char smem[];
    const uint32_t sbase = smem_u32(smem);
    const uint32_t mbF = sbase;           // full[5]
    const uint32_t mbE = sbase + 64;      // empty[5]
    const uint32_t dbase = sbase + 128;

    const int tid = threadIdx.x, lane = tid & 31, wid = tid >> 5;
    const int warp_m = wid & 1, warp_n = wid >> 1;     // 2 x 4 warps, 64x32 warp tiles
    const int m0 = blockIdx.y * 128, n0 = blockIdx.x * 128;

    const int lr = tid >> 2, lc = tid & 3;
    const __half* Ag = d_Ah + (size_t)m0 * IN_DIM;
    const __half* Bg = d_Bh + (size_t)n0 * IN_DIM;

    const uint32_t aLaneOff = (uint32_t)(lane & 15) * ROWB + (uint32_t)(lane >> 4) * 16;
    const uint32_t bLaneOff = (uint32_t)((lane & 7) + ((lane >> 4) << 3)) * ROWB
                            + (uint32_t)((lane >> 3) & 1) * 16;

    if (tid == 0) {
        #pragma unroll
        for (int s = 0; s < STAGES; s++) {
            MBAR_INIT(mbF + s * 8, 256);   // every thread's cp.async arrive (noinc)
            MBAR_INIT(mbE + s * 8, 8);     // one arrive per warp
        }
    }
    __syncthreads();

    float acc[4][4][4];
    #pragma unroll
    for (int i = 0; i < 4; i++)
        #pragma unroll
        for (int j = 0; j < 4; j++)
            #pragma unroll
            for (int q = 0; q < 4; q++) acc[i][j][q] = 0.f;

    auto issue_cp = [&](int t, int slot) {
        int kk = t << 5;
        uint32_t sA = dbase + slot * STAGE_BYTES;
        uint32_t sB = sA + ATILE_BYTES;
        CP_ASYNC16(sA + lr * ROWB + lc * 16,
                   (const char*)(Ag + (size_t)lr * IN_DIM + kk + lc * 8));
        CP_ASYNC16(sA + (lr + 64) * ROWB + lc * 16,
                   (const char*)(Ag + (size_t)(lr + 64) * IN_DIM + kk + lc * 8));
        CP_ASYNC16(sB + lr * ROWB + lc * 16,
                   (const char*)(Bg + (size_t)lr * IN_DIM + kk + lc * 8));
        CP_ASYNC16(sB + (lr + 64) * ROWB + lc * 16,
                   (const char*)(Bg + (size_t)(lr + 64) * IN_DIM + kk + lc * 8));
        CP_MBAR_ARRIVE(mbF + slot * 8);
    };

    // prologue: fill chunks 0..DEPTH-1 into slots 0..DEPTH-1
    #pragma unroll
    for (int f = 0; f < DEPTH; f++) issue_cp(f, f);

    int cs = 0, cpar = 0;      // consumer slot/parity
    int ps = DEPTH, ppar = 0;  // producer slot/parity

    for (int t = 0; t < NSTEP; t++) {
        int tf = t + DEPTH;
        if (tf < NSTEP) {
            if (tf >= STAGES) mbar_wait(mbE + ps * 8, ppar ^ 1);  // slot free?
            issue_cp(tf, ps);
            if (++ps == STAGES) { ps = 0; ppar ^= 1; }
        }

        mbar_wait(mbF + cs * 8, cpar);   // chunk t data ready (acquire)

        uint32_t sA = dbase + cs * STAGE_BYTES + (uint32_t)(warp_m * 64) * ROWB + aLaneOff;
        uint32_t sB = dbase + cs * STAGE_BYTES + ATILE_BYTES
                    + (uint32_t)(warp_n * 32) * ROWB + bLaneOff;
        #pragma unroll
        for (int k16 = 0; k16 < 2; k16++) {
            uint32_t a[4][4], b[2][4];
            #pragma unroll
            for (int mi = 0; mi < 4; mi++)
                ldm_x4(a[mi][0], a[mi][1], a[mi][2], a[mi][3],
                       sA + (uint32_t)(mi * 16) * ROWB + k16 * 32);
            #pragma unroll
            for (int p = 0; p < 2; p++)
                ldm_x4(b[p][0], b[p][1], b[p][2], b[p][3],
                       sB + (uint32_t)(p * 16) * ROWB + k16 * 32);
            #pragma unroll
            for (int mi = 0; mi < 4; mi++)
                #pragma unroll
                for (int ni = 0; ni < 4; ni++) {
                    uint32_t b0 = b[ni >> 1][(ni & 1) * 2];
                    uint32_t b1 = b[ni >> 1][(ni & 1) * 2 + 1];
                    mma_f16(acc[mi][ni][0], acc[mi][ni][1], acc[mi][ni][2], acc[mi][ni][3],
                            a[mi][0], a[mi][1], a[mi][2], a[mi][3], b0, b1);
                }
        }

        __syncwarp();
        if (lane == 0) MBAR_ARRIVE(mbE + cs * 8);   // this warp done with slot cs
        if (++cs == STAGES) { cs = 0; cpar ^= 1; }
    }

    // ---- epilogue: + bias, float2 stores (per-warp independent) ----
    #pragma unroll
    for (int ni = 0; ni < 4; ni++) {
        int col = n0 + warp_n * 32 + ni * 8 + (lane & 3) * 2;
        float2 bb = *(const float2*)(bias + col);
        #pragma unroll
        for (int mi = 0; mi < 4; mi++) {
            int r0 = m0 + warp_m * 64 + mi * 16 + (lane >> 2);
            float2 v0, v1;
            v0.x = acc[mi][ni][0] + bb.x; v0.y = acc[mi][ni][1] + bb.y;
            v1.x = acc[mi][ni][2] + bb.x; v1.y = acc[mi][ni][3] + bb.y;
            *(float2*)(y + (size_t)r0 * OUT_DIM + col)       = v0;
            *(float2*)(y + (size_t)(r0 + 8) * OUT_DIM + col) = v1;
        }
    }
}

// ---------------- host ----------------
extern "C" void kernel_launch(void* const* d_in, const int* in_sizes, int n_in,
                              void* d_out, int out_size) {
    const float* x       = (const float*)d_in[0];
    const int*   indices = (const int*)d_in[1];
    const float* lut     = (const float*)d_in[2];
    const float* sA      = (const float*)d_in[3];
    const float* sB      = (const float*)d_in[4];
    const float* mag     = (const float*)d_in[5];
    const float* bias    = (const float*)d_in[6];
    float*       y       = (float*)d_out;

    int M = in_sizes[0] / IN_DIM;   // 8192
    int xblk = (int)((size_t)M * IN_DIM / 4 / 256);          // 16384
    int wblk = (OUT_DIM * IN_DIM / 4) / 256;                 // 4096

    cudaFuncSetAttribute(gemm_kernel, cudaFuncAttributeMaxDynamicSharedMemorySize, SMEM_TOTAL);

    convert_kernel<<<8 + xblk + wblk, 256>>>(x, indices, lut, sA, sB, mag, xblk);
    gemm_kernel<<<dim3(OUT_DIM / 128, M / 128), 256, SMEM_TOTAL>>>(bias, y);
}